// round 7
// baseline (speedup 1.0000x reference)
#include <cuda_runtime.h>
#include <cuda_fp16.h>
#include <cstdint>

#define IN_F   4096
#define OUT_F  11008
#define M_TOT  512
#define BM     128
#define BN     128
#define BK     64
#define NCHUNK (IN_F / BK)      // 64
#define NTHREADS 512
#define NSTAGE 3
#define STAGE_BYTES 32768       // A 16KB + B 16KB

// x converted to fp16 once per launch (scratch: __device__ global, no allocs)
__device__ __align__(16) __half g_xh[M_TOT * IN_F];

// ---------------- helpers ----------------
__device__ __forceinline__ uint32_t smem_u32(const void* p) {
    uint32_t a;
    asm("{ .reg .u64 t; cvta.to.shared.u64 t, %1; cvt.u32.u64 %0, t; }" : "=r"(a) : "l"(p));
    return a;
}

#define LDSM4(r0, r1, r2, r3, addr) \
    asm volatile("ldmatrix.sync.aligned.m8n8.x4.shared.b16 {%0,%1,%2,%3}, [%4];" \
        : "=r"(r0), "=r"(r1), "=r"(r2), "=r"(r3) : "r"(addr))

#define MMA16816(c, a, b0, b1) \
    asm volatile("mma.sync.aligned.m16n8k16.row.col.f32.f16.f16.f32 " \
        "{%0,%1,%2,%3}, {%4,%5,%6,%7}, {%8,%9}, {%0,%1,%2,%3};" \
        : "+f"((c)[0]), "+f"((c)[1]), "+f"((c)[2]), "+f"((c)[3]) \
        : "r"((a)[0]), "r"((a)[1]), "r"((a)[2]), "r"((a)[3]), "r"(b0), "r"(b1))

#define CP_ASYNC16(dst, src) \
    asm volatile("cp.async.cg.shared.global [%0], [%1], 16;" :: "r"(dst), "l"(src) : "memory")
#define CP_ASYNC_COMMIT() asm volatile("cp.async.commit_group;" ::: "memory")
#define CP_ASYNC_WAIT1()  asm volatile("cp.async.wait_group 1;" ::: "memory")

__device__ __forceinline__ void sts128(uint32_t addr, uint4 v) {
    asm volatile("st.shared.v4.b32 [%0], {%1, %2, %3, %4};"
        :: "r"(addr), "r"(v.x), "r"(v.y), "r"(v.z), "r"(v.w) : "memory");
}

// dequant two int4-codes (stored as int32) -> packed fp16x2
__device__ __forceinline__ uint32_t packw(uint32_t q0, uint32_t q1, float s, float bz) {
    float f0 = fmaf((float)(int)q0, s, bz);
    float f1 = fmaf((float)(int)q1, s, bz);
    __half2 h = __floats2half2_rn(f0, f1);
    return *reinterpret_cast<uint32_t*>(&h);
}

#define SWZ(o) ((uint32_t)(o) ^ ((((uint32_t)(o)) >> 3) & 0x70))

// ---------------- kernel 1: x fp32 -> fp16 ----------------
__global__ void convert_x_kernel(const float* __restrict__ x) {
    int i = blockIdx.x * blockDim.x + threadIdx.x;   // 524288 threads, 4 elems each
    float4 v = reinterpret_cast<const float4*>(x)[i];
    __half2 a = __floats2half2_rn(v.x, v.y);
    __half2 b = __floats2half2_rn(v.z, v.w);
    uint2 u;
    u.x = *reinterpret_cast<uint32_t*>(&a);
    u.y = *reinterpret_cast<uint32_t*>(&b);
    reinterpret_cast<uint2*>(g_xh)[i] = u;
}

// ---------------- kernel 2: dequant + HMMA GEMM ----------------
// Dynamic smem: stage s (s=0..2) at s*32768:
//   A tile: 128 rows x 64 fp16 (128B/row, SW128)  -> offset 0     (16 KB)
//   B tile: 128 rows x 64 fp16 (128B/row, SW128)  -> offset 16384 (16 KB)
static constexpr int SMEM_BYTES = NSTAGE * STAGE_BYTES;   // 96 KB

__global__ __launch_bounds__(NTHREADS, 1)
void qlin_main_kernel(const int* __restrict__ qw,
                      const float* __restrict__ wsc,
                      const float* __restrict__ wzp,
                      const float* __restrict__ bias,
                      float* __restrict__ out) {
    extern __shared__ __align__(1024) char smem[];
    const uint32_t sb = smem_u32(smem);
    const int tid  = threadIdx.x;
    const int lane = tid & 31;
    const int wid  = tid >> 5;        // 16 warps
    const int mwarp = wid >> 2;       // 4 M-warps (32 rows each)
    const int nwarp = wid & 3;        // 4 N-warps (32 cols each)
    const int m0 = blockIdx.x * BM;   // 4 M-tiles (fast dim -> weight L2 reuse)
    const int n0 = blockIdx.y * BN;   // 86 N-tiles

    // ---- ldmatrix lane constants (SW128: addr = base ^ (ks<<5)) ----
    const int rA = lane & 15;
    const int cA = lane >> 4;                       // 0/1 (k halves)
    const int rB = (lane & 7) | (((lane >> 4) & 1) << 3);
    const int cB = (lane >> 3) & 1;
    uint32_t baseA[2], baseB[2];
    #pragma unroll
    for (int i = 0; i < 2; ++i) {
        const int row = mwarp * 32 + i * 16 + rA;
        baseA[i] = (uint32_t)(row * 128 + ((cA << 4) ^ ((row & 7) << 4)));
    }
    #pragma unroll
    for (int jj = 0; jj < 2; ++jj) {
        const int row = nwarp * 32 + jj * 16 + rB;
        baseB[jj] = (uint32_t)(16384 + row * 128 + ((cB << 4) ^ ((row & 7) << 4)));
    }

    // ---- loader lane constants ----
    // B: one row per thread group: 4 threads per row, 16 int32 codes each
    const int wrow  = tid >> 2;       // 0..127
    const int kpart = tid & 3;
    const uint32_t bo = (uint32_t)(wrow * 128 + kpart * 32);
    const uint32_t dstB0 = 16384u + SWZ(bo);
    const uint32_t dstB1 = 16384u + SWZ(bo + 16);
    // A: 2 cp.async chunks per thread
    uint32_t dstA[2];
    int rowA[2], prtA[2];
    #pragma unroll
    for (int t = 0; t < 2; ++t) {
        const int c = tid + t * NTHREADS;
        rowA[t] = c >> 3;
        prtA[t] = c & 7;
        dstA[t] = SWZ((uint32_t)(rowA[t] * 128 + prtA[t] * 16));
    }

    float acc[2][4][4];
    #pragma unroll
    for (int i = 0; i < 2; ++i)
        #pragma unroll
        for (int j = 0; j < 4; ++j)
            #pragma unroll
            for (int c = 0; c < 4; ++c) acc[i][j][c] = 0.f;

    uint4 q[4];
    float s_, bz_;

    const int rowB = n0 + wrow;
    const int* qrow = qw + (size_t)rowB * IN_F + kpart * 16;

    auto loadB = [&](int kc) {
        const int* p = qrow + kc * BK;
        q[0] = *reinterpret_cast<const uint4*>(p);
        q[1] = *reinterpret_cast<const uint4*>(p + 4);
        q[2] = *reinterpret_cast<const uint4*>(p + 8);
        q[3] = *reinterpret_cast<const uint4*>(p + 12);
        if ((kc & 1) == 0) {
            const int g = kc >> 1;
            const float s = wsc[rowB * 32 + g];
            s_ = s;
            bz_ = -wzp[rowB * 32 + g] * s;
        }
    };

    auto cpasyncA = [&](int kc, uint32_t stage) {
        #pragma unroll
        for (int t = 0; t < 2; ++t) {
            const __half* src = g_xh + (size_t)(m0 + rowA[t]) * IN_F + kc * BK + prtA[t] * 8;
            CP_ASYNC16(stage + dstA[t], src);
        }
        CP_ASYNC_COMMIT();
    };

    auto convertB = [&](uint32_t stage) {
        uint4 h0, h1;
        h0.x = packw(q[0].x, q[0].y, s_, bz_);  h0.y = packw(q[0].z, q[0].w, s_, bz_);
        h0.z = packw(q[1].x, q[1].y, s_, bz_);  h0.w = packw(q[1].z, q[1].w, s_, bz_);
        h1.x = packw(q[2].x, q[2].y, s_, bz_);  h1.y = packw(q[2].z, q[2].w, s_, bz_);
        h1.z = packw(q[3].x, q[3].y, s_, bz_);  h1.w = packw(q[3].z, q[3].w, s_, bz_);
        sts128(stage + dstB0, h0);
        sts128(stage + dstB1, h1);
    };

    auto mmaChunk = [&](uint32_t stage) {
        #pragma unroll
        for (int ks = 0; ks < 4; ++ks) {
            const uint32_t ax = (uint32_t)(ks << 5);
            uint32_t a[2][4];
            LDSM4(a[0][0], a[0][1], a[0][2], a[0][3], (stage + baseA[0]) ^ ax);
            LDSM4(a[1][0], a[1][1], a[1][2], a[1][3], (stage + baseA[1]) ^ ax);
            uint32_t bf[4][2];
            #pragma unroll
            for (int jj = 0; jj < 2; ++jj) {
                uint32_t r0, r1, r2, r3;
                LDSM4(r0, r1, r2, r3, (stage + baseB[jj]) ^ ax);
                bf[2 * jj][0] = r0;      bf[2 * jj][1] = r1;
                bf[2 * jj + 1][0] = r2;  bf[2 * jj + 1][1] = r3;
            }
            #pragma unroll
            for (int i = 0; i < 2; ++i)
                #pragma unroll
                for (int j = 0; j < 4; ++j)
                    MMA16816(acc[i][j], a[i], bf[j][0], bf[j][1]);
        }
    };

    // ---- prologue: A(0), A(1) in flight; B(0) converted to stage 0 ----
    const uint32_t st0 = sb;
    const uint32_t st1 = sb + STAGE_BYTES;
    loadB(0);
    cpasyncA(0, st0);
    cpasyncA(1, st1);
    convertB(st0);
    CP_ASYNC_WAIT1();            // A(0) complete
    __syncthreads();

    // ---- main loop: 3-stage, cp.async 2 ahead, weights 1 ahead ----
    for (int kc = 0; kc < NCHUNK; ++kc) {
        const uint32_t cur = sb + (uint32_t)((kc % NSTAGE) * STAGE_BYTES);
        const uint32_t nxt = sb + (uint32_t)(((kc + 1) % NSTAGE) * STAGE_BYTES);
        const uint32_t nn  = sb + (uint32_t)(((kc + 2) % NSTAGE) * STAGE_BYTES);
        if (kc + 1 < NCHUNK) loadB(kc + 1);      // LDG latency hides under MMA
        if (kc + 2 < NCHUNK) cpasyncA(kc + 2, nn);
        mmaChunk(cur);
        if (kc + 1 < NCHUNK) convertB(nxt);
        CP_ASYNC_WAIT1();                         // A(kc+1) complete
        __syncthreads();
    }

    // ---- epilogue: direct float2 stores + bias ----
    const int r_base = m0 + mwarp * 32 + (lane >> 2);
    #pragma unroll
    for (int j = 0; j < 4; ++j) {
        const int col = n0 + nwarp * 32 + j * 8 + (lane & 3) * 2;
        const float2 bv = *reinterpret_cast<const float2*>(&bias[col]);
        #pragma unroll
        for (int i = 0; i < 2; ++i) {
            const int r0 = r_base + i * 16;
            float2 v0 = make_float2(acc[i][j][0] + bv.x, acc[i][j][1] + bv.y);
            float2 v1 = make_float2(acc[i][j][2] + bv.x, acc[i][j][3] + bv.y);
            *reinterpret_cast<float2*>(&out[(size_t)r0 * OUT_F + col]) = v0;
            *reinterpret_cast<float2*>(&out[(size_t)(r0 + 8) * OUT_F + col]) = v1;
        }
    }
}

// ---------------- launch ----------------
extern "C" void kernel_launch(void* const* d_in, const int* in_sizes, int n_in,
                              void* d_out, int out_size) {
    (void)in_sizes; (void)n_in; (void)out_size;
    const float* x    = (const float*)d_in[0];
    const int*   qw   = (const int*)d_in[1];
    const float* wsc  = (const float*)d_in[2];
    const float* wzp  = (const float*)d_in[3];
    const float* bias = (const float*)d_in[4];
    float* out = (float*)d_out;

    cudaFuncSetAttribute(qlin_main_kernel,
                         cudaFuncAttributeMaxDynamicSharedMemorySize, SMEM_BYTES);

    convert_x_kernel<<<2048, 256>>>(x);
    qlin_main_kernel<<<dim3(4, 86), NTHREADS, SMEM_BYTES>>>(qw, wsc, wzp, bias, out);
}